// round 4
// baseline (speedup 1.0000x reference)
#include <cuda_runtime.h>
#include <cuda_bf16.h>

// Problem shape (fixed by reference):
//   b=16, c=512, h*w=4096
//   GEMM1 (NT): inter[b] = sigmoid( depth[b] (512x4096) @ rgb[b]^T (4096x512) )
//   GEMM2 (NN): out[b]   = rgb[b] + inter[b] (512x512) @ depth[b] (512x4096)

#define BATCH 16
#define CDIM  512
#define HW    4096

#define BM 128
#define BN 128
#define BK 8
#define TM 8
#define TN 8

// Scratch for interaction matrices: 16 * 512 * 512 floats = 16.78 MB
__device__ float g_inter[BATCH * CDIM * CDIM];

// ---------------------------------------------------------------------------
// GEMM1: C[m,n] = sigmoid( sum_s A[m,s] * B[n,s] )   (NT: both K-contiguous)
// A = depth (M=512, K=4096, lda=4096), B = rgb (N=512, K=4096, ldb=4096)
// ---------------------------------------------------------------------------
__global__ __launch_bounds__(256, 2)
void gemm1_nt_sigmoid(const float* __restrict__ depth,
                      const float* __restrict__ rgb) {
    const int b = blockIdx.z;
    const float* A = depth + (size_t)b * CDIM * HW;
    const float* B = rgb   + (size_t)b * CDIM * HW;
    float* C = g_inter + (size_t)b * CDIM * CDIM;

    __shared__ float As[BK][BM];
    __shared__ float Bs[BK][BN];

    const int tid = threadIdx.x;
    const int tx = tid % 16;           // 16 x 16 thread grid
    const int ty = tid / 16;

    // Load mapping: each thread loads one float4 of A tile and one of B tile.
    const int lrow  = tid >> 1;        // 0..127
    const int lcol4 = (tid & 1) * 4;   // 0 or 4

    const float* Arow = A + (size_t)(blockIdx.y * BM + lrow) * HW + lcol4;
    const float* Brow = B + (size_t)(blockIdx.x * BN + lrow) * HW + lcol4;

    float acc[TM][TN];
#pragma unroll
    for (int i = 0; i < TM; i++)
#pragma unroll
        for (int j = 0; j < TN; j++) acc[i][j] = 0.0f;

    for (int k0 = 0; k0 < HW; k0 += BK) {
        float4 av = *(const float4*)(Arow + k0);
        float4 bv = *(const float4*)(Brow + k0);
        As[lcol4 + 0][lrow] = av.x;
        As[lcol4 + 1][lrow] = av.y;
        As[lcol4 + 2][lrow] = av.z;
        As[lcol4 + 3][lrow] = av.w;
        Bs[lcol4 + 0][lrow] = bv.x;
        Bs[lcol4 + 1][lrow] = bv.y;
        Bs[lcol4 + 2][lrow] = bv.z;
        Bs[lcol4 + 3][lrow] = bv.w;
        __syncthreads();

#pragma unroll
        for (int k = 0; k < BK; k++) {
            float4 a0 = *(const float4*)&As[k][ty * TM];
            float4 a1 = *(const float4*)&As[k][ty * TM + 4];
            float4 b0 = *(const float4*)&Bs[k][tx * TN];
            float4 b1 = *(const float4*)&Bs[k][tx * TN + 4];
            float ra[TM] = {a0.x, a0.y, a0.z, a0.w, a1.x, a1.y, a1.z, a1.w};
            float rb[TN] = {b0.x, b0.y, b0.z, b0.w, b1.x, b1.y, b1.z, b1.w};
#pragma unroll
            for (int i = 0; i < TM; i++)
#pragma unroll
                for (int j = 0; j < TN; j++)
                    acc[i][j] = fmaf(ra[i], rb[j], acc[i][j]);
        }
        __syncthreads();
    }

    // Epilogue: sigmoid, store to scratch
    const int crow0 = blockIdx.y * BM + ty * TM;
    const int ccol0 = blockIdx.x * BN + tx * TN;
#pragma unroll
    for (int i = 0; i < TM; i++) {
        float* crow = C + (size_t)(crow0 + i) * CDIM + ccol0;
#pragma unroll
        for (int j = 0; j < TN; j += 4) {
            float4 v;
            v.x = 1.0f / (1.0f + __expf(-acc[i][j + 0]));
            v.y = 1.0f / (1.0f + __expf(-acc[i][j + 1]));
            v.z = 1.0f / (1.0f + __expf(-acc[i][j + 2]));
            v.w = 1.0f / (1.0f + __expf(-acc[i][j + 3]));
            *(float4*)(crow + j) = v;
        }
    }
}

// ---------------------------------------------------------------------------
// GEMM2: out[m,s] = rgb[m,s] + sum_d A[m,d] * B[d,s]   (NN)
// A = inter (M=512, K=512, lda=512), B = depth (K=512, N=4096, ldb=4096)
// ---------------------------------------------------------------------------
__global__ __launch_bounds__(256, 2)
void gemm2_nn_add(const float* __restrict__ depth,
                  const float* __restrict__ rgb,
                  float* __restrict__ out) {
    const int b = blockIdx.z;
    const float* A = g_inter + (size_t)b * CDIM * CDIM;
    const float* B = depth   + (size_t)b * CDIM * HW;
    const float* R = rgb     + (size_t)b * CDIM * HW;
    float*       O = out     + (size_t)b * CDIM * HW;

    __shared__ float As[BK][BM];
    __shared__ float Bs[BK][BN];

    const int tid = threadIdx.x;
    const int tx = tid % 16;
    const int ty = tid / 16;

    // A tile load (K-contiguous rows, transpose into smem)
    const int larow  = tid >> 1;        // 0..127
    const int lacol4 = (tid & 1) * 4;   // 0 or 4
    const float* Arow = A + (size_t)(blockIdx.y * BM + larow) * CDIM + lacol4;

    // B tile load (N-contiguous rows, direct)
    const int lbrow  = tid >> 5;        // 0..7
    const int lbcol4 = (tid & 31) * 4;  // 0..124
    const float* Bbase = B + (size_t)lbrow * HW + blockIdx.x * BN + lbcol4;

    float acc[TM][TN];
#pragma unroll
    for (int i = 0; i < TM; i++)
#pragma unroll
        for (int j = 0; j < TN; j++) acc[i][j] = 0.0f;

    for (int k0 = 0; k0 < CDIM; k0 += BK) {
        float4 av = *(const float4*)(Arow + k0);
        float4 bv = *(const float4*)(Bbase + (size_t)k0 * HW);
        As[lacol4 + 0][larow] = av.x;
        As[lacol4 + 1][larow] = av.y;
        As[lacol4 + 2][larow] = av.z;
        As[lacol4 + 3][larow] = av.w;
        *(float4*)&Bs[lbrow][lbcol4] = bv;
        __syncthreads();

#pragma unroll
        for (int k = 0; k < BK; k++) {
            float4 a0 = *(const float4*)&As[k][ty * TM];
            float4 a1 = *(const float4*)&As[k][ty * TM + 4];
            float4 b0 = *(const float4*)&Bs[k][tx * TN];
            float4 b1 = *(const float4*)&Bs[k][tx * TN + 4];
            float ra[TM] = {a0.x, a0.y, a0.z, a0.w, a1.x, a1.y, a1.z, a1.w};
            float rb[TN] = {b0.x, b0.y, b0.z, b0.w, b1.x, b1.y, b1.z, b1.w};
#pragma unroll
            for (int i = 0; i < TM; i++)
#pragma unroll
                for (int j = 0; j < TN; j++)
                    acc[i][j] = fmaf(ra[i], rb[j], acc[i][j]);
        }
        __syncthreads();
    }

    // Epilogue: add rgb residual, store out
    const int orow0 = blockIdx.y * BM + ty * TM;
    const int ocol0 = blockIdx.x * BN + tx * TN;
#pragma unroll
    for (int i = 0; i < TM; i++) {
        const float* rrow = R + (size_t)(orow0 + i) * HW + ocol0;
        float*       orow = O + (size_t)(orow0 + i) * HW + ocol0;
#pragma unroll
        for (int j = 0; j < TN; j += 4) {
            float4 r = *(const float4*)(rrow + j);
            float4 v;
            v.x = acc[i][j + 0] + r.x;
            v.y = acc[i][j + 1] + r.y;
            v.z = acc[i][j + 2] + r.z;
            v.w = acc[i][j + 3] + r.w;
            *(float4*)(orow + j) = v;
        }
    }
}

extern "C" void kernel_launch(void* const* d_in, const int* in_sizes, int n_in,
                              void* d_out, int out_size) {
    const float* rgb   = (const float*)d_in[0];
    const float* depth = (const float*)d_in[1];
    float* out = (float*)d_out;

    // GEMM1: M=N=512 -> 4x4 tiles per batch
    dim3 g1(CDIM / BN, CDIM / BM, BATCH);
    gemm1_nt_sigmoid<<<g1, 256>>>(depth, rgb);

    // GEMM2: M=512, N=4096 -> 32x4 tiles per batch
    dim3 g2(HW / BN, CDIM / BM, BATCH);
    gemm2_nn_add<<<g2, 256>>>(depth, rgb, out);
}

// round 7
// speedup vs baseline: 2.8265x; 2.8265x over previous
#include <cuda_runtime.h>
#include <cuda_bf16.h>
#include <cstdint>

// ---------------------------------------------------------------------------
// b=16, c=512, hw=4096
//   inter = sigmoid(depth @ rgb^T)            (512x512, K=4096, NT)
//   out   = rgb + inter @ depthT^T            (512x4096, K=512,  NT)
// Path: mma.sync (HMMA) bf16, 3-pass split precision, fp32 accumulation.
// (tcgen05 PTX is rejected by this toolchain's .target sm_103.)
// ---------------------------------------------------------------------------

#define BATCH 16
#define CDIM  512
#define HW    4096

#define BM 128
#define BN 128
#define BK 64

#define OFF_AHI 0
#define OFF_ALO 16384
#define OFF_BHI 32768
#define OFF_BLO 49152
#define STAGE   65536
#define SMEM_TOTAL (2 * STAGE)

// ---------------------------------------------------------------------------
// Scratch (__device__ globals; allocation-guard-safe)
// ---------------------------------------------------------------------------
__device__ __align__(128) __nv_bfloat16 g_depth_hi [BATCH * CDIM * HW];   // [b,c,s]
__device__ __align__(128) __nv_bfloat16 g_depth_lo [BATCH * CDIM * HW];
__device__ __align__(128) __nv_bfloat16 g_rgb_hi   [BATCH * CDIM * HW];   // [b,c,s]
__device__ __align__(128) __nv_bfloat16 g_rgb_lo   [BATCH * CDIM * HW];
__device__ __align__(128) __nv_bfloat16 g_depthT_hi[BATCH * HW * CDIM];   // [b,s,c]
__device__ __align__(128) __nv_bfloat16 g_depthT_lo[BATCH * HW * CDIM];
__device__ __align__(128) __nv_bfloat16 g_inter_hi [BATCH * CDIM * CDIM]; // [b,c,d]
__device__ __align__(128) __nv_bfloat16 g_inter_lo [BATCH * CDIM * CDIM];

// ---------------------------------------------------------------------------
// PTX helpers (all sm_80-era: compile under plain compute_103)
// ---------------------------------------------------------------------------
__device__ __forceinline__ uint32_t smem_u32(const void* p) {
    uint32_t a;
    asm("{ .reg .u64 t; cvta.to.shared.u64 t, %1; cvt.u32.u64 %0, t; }"
        : "=r"(a) : "l"(p));
    return a;
}

__device__ __forceinline__ void cpasync16(uint32_t s, const void* g) {
    asm volatile("cp.async.cg.shared.global [%0], [%1], 16;" :: "r"(s), "l"(g));
}
#define CP_COMMIT() asm volatile("cp.async.commit_group;" ::: "memory")
#define CP_WAIT1()  asm volatile("cp.async.wait_group 1;" ::: "memory")

__device__ __forceinline__ void ldsm4(uint32_t (&r)[4], uint32_t a) {
    asm volatile("ldmatrix.sync.aligned.m8n8.x4.shared.b16 {%0,%1,%2,%3}, [%4];"
                 : "=r"(r[0]), "=r"(r[1]), "=r"(r[2]), "=r"(r[3]) : "r"(a));
}

__device__ __forceinline__ void mma16816(float (&d)[4], const uint32_t (&a)[4],
                                         uint32_t b0, uint32_t b1) {
    asm volatile(
        "mma.sync.aligned.m16n8k16.row.col.f32.bf16.bf16.f32 "
        "{%0,%1,%2,%3},{%4,%5,%6,%7},{%8,%9},{%0,%1,%2,%3};"
        : "+f"(d[0]), "+f"(d[1]), "+f"(d[2]), "+f"(d[3])
        : "r"(a[0]), "r"(a[1]), "r"(a[2]), "r"(a[3]), "r"(b0), "r"(b1));
}

// Swizzle: XOR byte-offset bits [4:6] with bits [7:9].  Rows are 128B.
// Same formula at store (cp.async dst) and load (ldmatrix) -> any base works.
__device__ __forceinline__ uint32_t sw(uint32_t off) {
    return off ^ ((off >> 3) & 0x70);
}

// ---------------------------------------------------------------------------
// Producer: one pipeline stage (Ahi/Alo: 128x64, Bhi/Blo: 128x64 bf16)
// 256 threads, 16B per cp.async, 16 per thread.
// ---------------------------------------------------------------------------
__device__ __forceinline__ void produce(
    uint32_t sb, int stage,
    const __nv_bfloat16* __restrict__ Ahi, const __nv_bfloat16* __restrict__ Alo,
    const __nv_bfloat16* __restrict__ Bhi, const __nv_bfloat16* __restrict__ Blo,
    int lda, int ldb, int kcol)
{
    const int tid = threadIdx.x;
    const int c = tid & 7;          // 16B chunk in row
    const int r0 = tid >> 3;        // base row, +32 per iteration
    const uint32_t s0 = sb + stage * STAGE;
#pragma unroll
    for (int t = 0; t < 4; ++t) {
        const int row = r0 + 32 * t;
        const uint32_t off = sw((uint32_t)row * 128u + (uint32_t)c * 16u);
        const size_t ga = (size_t)row * lda + kcol + c * 8;
        const size_t gb = (size_t)row * ldb + kcol + c * 8;
        cpasync16(s0 + OFF_AHI + off, Ahi + ga);
        cpasync16(s0 + OFF_ALO + off, Alo + ga);
        cpasync16(s0 + OFF_BHI + off, Bhi + gb);
        cpasync16(s0 + OFF_BLO + off, Blo + gb);
    }
    CP_COMMIT();
}

// ---------------------------------------------------------------------------
// Consumer: one stage = 4 k16 steps, 3-pass split MMA.
// 8 warps as 2(m) x 4(n); warp tile 64x32. acc[t:4 m16][nidx:4 n8][4]
// ---------------------------------------------------------------------------
__device__ __forceinline__ void consume(uint32_t sb, int stage,
                                        float (&acc)[4][4][4]) {
    const int tid = threadIdx.x;
    const int lane = tid & 31, wid = tid >> 5;
    const int wm = wid >> 2, wn = wid & 3;
    const uint32_t s0 = sb + stage * STAGE;

    // A ldmatrix lanes: 0-15 -> rows m0..15 chunk0, 16-31 -> rows m0..15 chunk1
    const int a_r = lane & 15, a_c = lane >> 4;
    // B ldmatrix lanes: 0-7 n0-7 k0, 8-15 n0-7 k1, 16-23 n8-15 k0, 24-31 n8-15 k1
    const int b_n = ((lane >> 4) << 3) + (lane & 7);
    const int b_c = (lane >> 3) & 1;

#pragma unroll
    for (int kk = 0; kk < 4; ++kk) {
        uint32_t bh[2][4], bl[2][4];
#pragma unroll
        for (int u = 0; u < 2; ++u) {
            const uint32_t off =
                sw((uint32_t)(wn * 32 + u * 16 + b_n) * 128u +
                   (uint32_t)(kk * 2 + b_c) * 16u);
            ldsm4(bh[u], s0 + OFF_BHI + off);
            ldsm4(bl[u], s0 + OFF_BLO + off);
        }
#pragma unroll
        for (int t = 0; t < 4; ++t) {
            uint32_t ah[4], al[4];
            const uint32_t off =
                sw((uint32_t)(wm * 64 + t * 16 + a_r) * 128u +
                   (uint32_t)(kk * 2 + a_c) * 16u);
            ldsm4(ah, s0 + OFF_AHI + off);
            ldsm4(al, s0 + OFF_ALO + off);
#pragma unroll
            for (int u = 0; u < 2; ++u) {
#pragma unroll
                for (int h = 0; h < 2; ++h) {
                    float (&d)[4] = acc[t][u * 2 + h];
                    mma16816(d, ah, bh[u][h * 2], bh[u][h * 2 + 1]);
                    mma16816(d, ah, bl[u][h * 2], bl[u][h * 2 + 1]);
                    mma16816(d, al, bh[u][h * 2], bh[u][h * 2 + 1]);
                }
            }
        }
    }
}

__device__ __forceinline__ void mainloop(
    uint32_t sb, float (&acc)[4][4][4],
    const __nv_bfloat16* Ahi, const __nv_bfloat16* Alo,
    const __nv_bfloat16* Bhi, const __nv_bfloat16* Blo,
    int lda, int ldb, int nch)
{
#pragma unroll
    for (int t = 0; t < 4; ++t)
#pragma unroll
        for (int n = 0; n < 4; ++n)
#pragma unroll
            for (int r = 0; r < 4; ++r) acc[t][n][r] = 0.0f;

    produce(sb, 0, Ahi, Alo, Bhi, Blo, lda, ldb, 0);
    produce(sb, 1, Ahi, Alo, Bhi, Blo, lda, ldb, BK);
    for (int c = 0; c < nch; ++c) {
        CP_WAIT1();
        __syncthreads();
        consume(sb, c & 1, acc);
        __syncthreads();
        if (c + 2 < nch)
            produce(sb, c & 1, Ahi, Alo, Bhi, Blo, lda, ldb, (c + 2) * BK);
    }
}

__device__ __forceinline__ float sigmoidf(float x) {
    return 1.0f / (1.0f + __expf(-x));
}

// ---------------------------------------------------------------------------
// GEMM1: inter = sigmoid(depth @ rgb^T); epilogue splits to bf16 hi/lo
// grid (4, 4, 16), 256 threads
// ---------------------------------------------------------------------------
__global__ __launch_bounds__(256, 1)
void gemm1_tc() {
    extern __shared__ char smem[];
    const uint32_t sb = smem_u32(smem);
    const int b = blockIdx.z;
    const size_t aoff = ((size_t)b * CDIM + blockIdx.y * BM) * HW;
    const size_t boff = ((size_t)b * CDIM + blockIdx.x * BN) * HW;

    float acc[4][4][4];
    mainloop(sb, acc, g_depth_hi + aoff, g_depth_lo + aoff,
             g_rgb_hi + boff, g_rgb_lo + boff, HW, HW, HW / BK);

    const int lane = threadIdx.x & 31, wid = threadIdx.x >> 5;
    const int wm = wid >> 2, wn = wid & 3;
    const int r0 = blockIdx.y * BM + wm * 64 + (lane >> 2);
    const int c0 = blockIdx.x * BN + wn * 32 + (lane & 3) * 2;
    __nv_bfloat16* ih = g_inter_hi + (size_t)b * CDIM * CDIM;
    __nv_bfloat16* il = g_inter_lo + (size_t)b * CDIM * CDIM;
#pragma unroll
    for (int t = 0; t < 4; ++t) {
#pragma unroll
        for (int nidx = 0; nidx < 4; ++nidx) {
            const int n = c0 + nidx * 8;
#pragma unroll
            for (int half = 0; half < 2; ++half) {
                const int m = r0 + t * 16 + half * 8;
                const float v0 = sigmoidf(acc[t][nidx][half * 2 + 0]);
                const float v1 = sigmoidf(acc[t][nidx][half * 2 + 1]);
                const __nv_bfloat16 h0 = __float2bfloat16(v0);
                const __nv_bfloat16 h1 = __float2bfloat16(v1);
                const __nv_bfloat16 l0 = __float2bfloat16(v0 - __bfloat162float(h0));
                const __nv_bfloat16 l1 = __float2bfloat16(v1 - __bfloat162float(h1));
                const size_t idx = (size_t)m * CDIM + n;
                *(__nv_bfloat162*)(ih + idx) = __nv_bfloat162(h0, h1);
                *(__nv_bfloat162*)(il + idx) = __nv_bfloat162(l0, l1);
            }
        }
    }
}

// ---------------------------------------------------------------------------
// GEMM2: out = rgb + inter @ depthT^T; grid (32, 4, 16), 256 threads
// ---------------------------------------------------------------------------
__global__ __launch_bounds__(256, 1)
void gemm2_tc(const float* __restrict__ rgb, float* __restrict__ out) {
    extern __shared__ char smem[];
    const uint32_t sb = smem_u32(smem);
    const int b = blockIdx.z;
    const size_t aoff = ((size_t)b * CDIM + blockIdx.y * BM) * CDIM;
    const size_t boff = ((size_t)b * HW + blockIdx.x * BN) * CDIM;

    float acc[4][4][4];
    mainloop(sb, acc, g_inter_hi + aoff, g_inter_lo + aoff,
             g_depthT_hi + boff, g_depthT_lo + boff, CDIM, CDIM, CDIM / BK);

    const int lane = threadIdx.x & 31, wid = threadIdx.x >> 5;
    const int wm = wid >> 2, wn = wid & 3;
    const int r0 = blockIdx.y * BM + wm * 64 + (lane >> 2);
    const int c0 = blockIdx.x * BN + wn * 32 + (lane & 3) * 2;
    const size_t base = (size_t)b * CDIM * HW;
#pragma unroll
    for (int t = 0; t < 4; ++t) {
#pragma unroll
        for (int nidx = 0; nidx < 4; ++nidx) {
            const int n = c0 + nidx * 8;
#pragma unroll
            for (int half = 0; half < 2; ++half) {
                const int m = r0 + t * 16 + half * 8;
                const size_t idx = base + (size_t)m * HW + n;
                const float2 rv = *(const float2*)(rgb + idx);
                float2 v;
                v.x = acc[t][nidx][half * 2 + 0] + rv.x;
                v.y = acc[t][nidx][half * 2 + 1] + rv.y;
                *(float2*)(out + idx) = v;
            }
        }
    }
}

// ---------------------------------------------------------------------------
// rgb split: fp32 -> bf16 hi/lo, 8 elems/thread
// ---------------------------------------------------------------------------
__global__ __launch_bounds__(256)
void split_rgb_kernel(const float* __restrict__ rgb) {
    const size_t i = ((size_t)blockIdx.x * 256 + threadIdx.x) * 8;
    float4 a = *(const float4*)(rgb + i);
    float4 c = *(const float4*)(rgb + i + 4);
    float v[8] = {a.x, a.y, a.z, a.w, c.x, c.y, c.z, c.w};
    union { __nv_bfloat16 h[8]; uint4 u; } H, L;
#pragma unroll
    for (int j = 0; j < 8; ++j) {
        __nv_bfloat16 hb = __float2bfloat16(v[j]);
        H.h[j] = hb;
        L.h[j] = __float2bfloat16(v[j] - __bfloat162float(hb));
    }
    *(uint4*)(g_rgb_hi + i) = H.u;
    *(uint4*)(g_rgb_lo + i) = L.u;
}

// ---------------------------------------------------------------------------
// depth: fused split (straight) + transposed split.  [b,c,s] -> hi/lo and
// [b,s,c] hi/lo.  grid (HW/32, CDIM/32, BATCH), block (32, 8)
// ---------------------------------------------------------------------------
__global__ __launch_bounds__(256)
void depth_split_transpose_kernel(const float* __restrict__ depth) {
    __shared__ float tbuf[32][33];
    const int b = blockIdx.z;
    const int s0 = blockIdx.x * 32;
    const int c0 = blockIdx.y * 32;
    const int tx = threadIdx.x, ty = threadIdx.y;

    const float* src = depth + ((size_t)b * CDIM + c0) * HW + s0;
#pragma unroll
    for (int i = 0; i < 32; i += 8) {
        const float v = src[(size_t)(ty + i) * HW + tx];
        tbuf[ty + i][tx] = v;
        const __nv_bfloat16 hb = __float2bfloat16(v);
        const size_t di = ((size_t)b * CDIM + c0 + ty + i) * HW + s0 + tx;
        g_depth_hi[di] = hb;
        g_depth_lo[di] = __float2bfloat16(v - __bfloat162float(hb));
    }
    __syncthreads();

    __nv_bfloat16* dh = g_depthT_hi + ((size_t)b * HW + s0) * CDIM + c0;
    __nv_bfloat16* dl = g_depthT_lo + ((size_t)b * HW + s0) * CDIM + c0;
#pragma unroll
    for (int i = 0; i < 32; i += 8) {
        const float v = tbuf[tx][ty + i];
        const __nv_bfloat16 hb = __float2bfloat16(v);
        dh[(size_t)(ty + i) * CDIM + tx] = hb;
        dl[(size_t)(ty + i) * CDIM + tx] =
            __float2bfloat16(v - __bfloat162float(hb));
    }
}

// ---------------------------------------------------------------------------
// Launch
// ---------------------------------------------------------------------------
extern "C" void kernel_launch(void* const* d_in, const int* in_sizes, int n_in,
                              void* d_out, int out_size) {
    const float* rgb   = (const float*)d_in[0];
    const float* depth = (const float*)d_in[1];
    float* out = (float*)d_out;

    static bool attr_done = false;
    if (!attr_done) {
        cudaFuncSetAttribute(gemm1_tc,
                             cudaFuncAttributeMaxDynamicSharedMemorySize, SMEM_TOTAL);
        cudaFuncSetAttribute(gemm2_tc,
                             cudaFuncAttributeMaxDynamicSharedMemorySize, SMEM_TOTAL);
        attr_done = true;
    }

    const size_t TOT = (size_t)BATCH * CDIM * HW;   // 33,554,432
    split_rgb_kernel<<<(unsigned)(TOT / 8 / 256), 256>>>(rgb);
    depth_split_transpose_kernel<<<dim3(HW / 32, CDIM / 32, BATCH),
                                   dim3(32, 8)>>>(depth);

    gemm1_tc<<<dim3(CDIM / BN, CDIM / BM, BATCH), 256, SMEM_TOTAL>>>();
    gemm2_tc<<<dim3(HW / BN, CDIM / BM, BATCH), 256, SMEM_TOTAL>>>(rgb, out);
}

// round 8
// speedup vs baseline: 2.9223x; 1.0339x over previous
#include <cuda_runtime.h>
#include <cuda_bf16.h>
#include <cstdint>

// ---------------------------------------------------------------------------
// b=16, c=512, hw=4096
//   inter = sigmoid(depth @ rgb^T)    (512x512, K=4096, NT)
//   out   = rgb + inter @ depth       (512x4096, K=512; B read via ldsm.trans)
// mma.sync bf16 3-pass split precision, fp32 accum.
// BK=32, 3 stages, 2 CTAs/SM (launch_bounds 256,2), SW64 swizzle (64B rows).
// ---------------------------------------------------------------------------

#define BATCH 16
#define CDIM  512
#define HW    4096

#define BM 128
#define BN 128
#define BK 32

#define OFF_AHI 0
#define OFF_ALO 8192
#define OFF_BHI 16384
#define OFF_BLO 24576
#define STAGE   32768
#define NSTAGE  3
#define SMEM_TOTAL (NSTAGE * STAGE)   // 96 KB per CTA

// ---------------------------------------------------------------------------
// Scratch (__device__ globals; allocation-guard-safe)
// ---------------------------------------------------------------------------
__device__ __align__(128) __nv_bfloat16 g_depth_hi[BATCH * CDIM * HW];   // [b,c,s]
__device__ __align__(128) __nv_bfloat16 g_depth_lo[BATCH * CDIM * HW];
__device__ __align__(128) __nv_bfloat16 g_rgb_hi  [BATCH * CDIM * HW];   // [b,c,s]
__device__ __align__(128) __nv_bfloat16 g_rgb_lo  [BATCH * CDIM * HW];
__device__ __align__(128) __nv_bfloat16 g_inter_hi[BATCH * CDIM * CDIM]; // [b,c,d]
__device__ __align__(128) __nv_bfloat16 g_inter_lo[BATCH * CDIM * CDIM];

// ---------------------------------------------------------------------------
// PTX helpers (sm_80-era; compile under plain compute_103)
// ---------------------------------------------------------------------------
__device__ __forceinline__ uint32_t smem_u32(const void* p) {
    uint32_t a;
    asm("{ .reg .u64 t; cvta.to.shared.u64 t, %1; cvt.u32.u64 %0, t; }"
        : "=r"(a) : "l"(p));
    return a;
}

__device__ __forceinline__ void cpasync16(uint32_t s, const void* g) {
    asm volatile("cp.async.cg.shared.global [%0], [%1], 16;" :: "r"(s), "l"(g));
}
#define CP_COMMIT() asm volatile("cp.async.commit_group;" ::: "memory")
#define CP_WAIT2()  asm volatile("cp.async.wait_group 2;" ::: "memory")

__device__ __forceinline__ void ldsm4(uint32_t (&r)[4], uint32_t a) {
    asm volatile("ldmatrix.sync.aligned.m8n8.x4.shared.b16 {%0,%1,%2,%3}, [%4];"
                 : "=r"(r[0]), "=r"(r[1]), "=r"(r[2]), "=r"(r[3]) : "r"(a));
}
__device__ __forceinline__ void ldsm4t(uint32_t (&r)[4], uint32_t a) {
    asm volatile("ldmatrix.sync.aligned.m8n8.x4.trans.shared.b16 {%0,%1,%2,%3}, [%4];"
                 : "=r"(r[0]), "=r"(r[1]), "=r"(r[2]), "=r"(r[3]) : "r"(a));
}

__device__ __forceinline__ void mma16816(float (&d)[4], const uint32_t (&a)[4],
                                         uint32_t b0, uint32_t b1) {
    asm volatile(
        "mma.sync.aligned.m16n8k16.row.col.f32.bf16.bf16.f32 "
        "{%0,%1,%2,%3},{%4,%5,%6,%7},{%8,%9},{%0,%1,%2,%3};"
        : "+f"(d[0]), "+f"(d[1]), "+f"(d[2]), "+f"(d[3])
        : "r"(a[0]), "r"(a[1]), "r"(a[2]), "r"(a[3]), "r"(b0), "r"(b1));
}

// SW64 swizzle for 64-byte rows: XOR bits[4:5] with bits[7:8].
// Same formula at cp.async store and ldmatrix load -> consistent; conflict-free.
__device__ __forceinline__ uint32_t sw(uint32_t off) {
    return off ^ ((off >> 3) & 0x30);
}

// ---------------------------------------------------------------------------
// Producer: one stage. A: BMx32 (m-major, 64B rows). B:
//   !TRANSB: BNx32 n-major (64B rows), same addressing as A.
//   TRANSB : 32xBN k-major source (depth straight); stored as 4 subtiles of
//            32 rows(k) x 32 cols(n), 64B rows, sw() within each subtile.
// 512 16B-chunks per tile; 256 threads x 2 chunks.
// ---------------------------------------------------------------------------
template <bool TRANSB>
__device__ __forceinline__ void produce(
    uint32_t sb, int stage,
    const __nv_bfloat16* __restrict__ Ahi, const __nv_bfloat16* __restrict__ Alo,
    const __nv_bfloat16* __restrict__ Bhi, const __nv_bfloat16* __restrict__ Blo,
    int lda, int ldb, int kcol)
{
    const int tid = threadIdx.x;
    const uint32_t s0 = sb + stage * STAGE;
#pragma unroll
    for (int i = 0; i < 2; ++i) {
        const int id = tid + 256 * i;
        // A tile
        {
            const int row = id >> 2, c = id & 3;
            const uint32_t off = sw((uint32_t)row * 64u + (uint32_t)c * 16u);
            const size_t ga = (size_t)row * lda + kcol + c * 8;
            cpasync16(s0 + OFF_AHI + off, Ahi + ga);
            cpasync16(s0 + OFF_ALO + off, Alo + ga);
        }
        // B tile
        if (!TRANSB) {
            const int row = id >> 2, c = id & 3;
            const uint32_t off = sw((uint32_t)row * 64u + (uint32_t)c * 16u);
            const size_t gb = (size_t)row * ldb + kcol + c * 8;
            cpasync16(s0 + OFF_BHI + off, Bhi + gb);
            cpasync16(s0 + OFF_BLO + off, Blo + gb);
        } else {
            const int h = id >> 7, k = (id >> 2) & 31, cn = id & 3;
            const uint32_t off = (uint32_t)h * 2048u +
                                 sw((uint32_t)k * 64u + (uint32_t)cn * 16u);
            const size_t gb = (size_t)(kcol + k) * ldb + h * 32 + cn * 8;
            cpasync16(s0 + OFF_BHI + off, Bhi + gb);
            cpasync16(s0 + OFF_BLO + off, Blo + gb);
        }
    }
    CP_COMMIT();
}

// ---------------------------------------------------------------------------
// Consumer: one stage = 2 k16 steps, 3-pass split MMA.
// 8 warps as 2(m) x 4(n); warp tile 64x32. acc[t:4 m16][nidx:4 n8][4].
// ---------------------------------------------------------------------------
template <bool TRANSB>
__device__ __forceinline__ void consume(uint32_t sb, int stage,
                                        float (&acc)[4][4][4]) {
    const int tid = threadIdx.x;
    const int lane = tid & 31, wid = tid >> 5;
    const int wm = wid >> 2, wn = wid & 3;
    const uint32_t s0 = sb + stage * STAGE;

    // A ldmatrix lanes (non-trans): rows m, 2 k-chunks
    const int a_r = lane & 15, a_c = lane >> 4;
    // B non-trans lanes: n-rows + k-chunk
    const int b_n = ((lane >> 4) << 3) + (lane & 7);
    const int b_c = (lane >> 3) & 1;
    // B trans lanes: k-rows + n-chunk
    const int bt_k = ((lane >> 3) & 1) * 8 + (lane & 7);
    const int bt_u = lane >> 4;

#pragma unroll
    for (int kk = 0; kk < 2; ++kk) {
        uint32_t bh[2][4], bl[2][4];
#pragma unroll
        for (int u = 0; u < 2; ++u) {
            if (!TRANSB) {
                const uint32_t off =
                    sw((uint32_t)(wn * 32 + u * 16 + b_n) * 64u +
                       (uint32_t)(kk * 2 + b_c) * 16u);
                ldsm4(bh[u], s0 + OFF_BHI + off);
                ldsm4(bl[u], s0 + OFF_BLO + off);
            } else {
                const uint32_t off = (uint32_t)wn * 2048u +
                    sw((uint32_t)(kk * 16 + bt_k) * 64u +
                       (uint32_t)(u * 2 + bt_u) * 16u);
                ldsm4t(bh[u], s0 + OFF_BHI + off);
                ldsm4t(bl[u], s0 + OFF_BLO + off);
            }
        }
#pragma unroll
        for (int t = 0; t < 4; ++t) {
            uint32_t ah[4], al[4];
            const uint32_t off =
                sw((uint32_t)(wm * 64 + t * 16 + a_r) * 64u +
                   (uint32_t)(kk * 2 + a_c) * 16u);
            ldsm4(ah, s0 + OFF_AHI + off);
            ldsm4(al, s0 + OFF_ALO + off);
#pragma unroll
            for (int u = 0; u < 2; ++u) {
#pragma unroll
                for (int h = 0; h < 2; ++h) {
                    float (&d)[4] = acc[t][u * 2 + h];
                    mma16816(d, ah, bh[u][h * 2], bh[u][h * 2 + 1]);
                    mma16816(d, ah, bl[u][h * 2], bl[u][h * 2 + 1]);
                    mma16816(d, al, bh[u][h * 2], bh[u][h * 2 + 1]);
                }
            }
        }
    }
}

template <bool TRANSB>
__device__ __forceinline__ void mainloop(
    uint32_t sb, float (&acc)[4][4][4],
    const __nv_bfloat16* Ahi, const __nv_bfloat16* Alo,
    const __nv_bfloat16* Bhi, const __nv_bfloat16* Blo,
    int lda, int ldb, int nch)
{
#pragma unroll
    for (int t = 0; t < 4; ++t)
#pragma unroll
        for (int n = 0; n < 4; ++n)
#pragma unroll
            for (int r = 0; r < 4; ++r) acc[t][n][r] = 0.0f;

    // Prime 3 stages (empty commit keeps group accounting uniform)
#pragma unroll
    for (int cc = 0; cc < NSTAGE; ++cc) {
        if (cc < nch)
            produce<TRANSB>(sb, cc, Ahi, Alo, Bhi, Blo, lda, ldb, cc * BK);
        else
            CP_COMMIT();
    }
    for (int c = 0; c < nch; ++c) {
        CP_WAIT2();
        __syncthreads();
        consume<TRANSB>(sb, c % NSTAGE, acc);
        __syncthreads();
        if (c + NSTAGE < nch)
            produce<TRANSB>(sb, c % NSTAGE, Ahi, Alo, Bhi, Blo, lda, ldb,
                            (c + NSTAGE) * BK);
        else
            CP_COMMIT();
    }
}

__device__ __forceinline__ float sigmoidf(float x) {
    return 1.0f / (1.0f + __expf(-x));
}

// ---------------------------------------------------------------------------
// GEMM1: inter = sigmoid(depth @ rgb^T); epilogue splits to bf16 hi/lo
// grid (4, 4, 16), 256 threads
// ---------------------------------------------------------------------------
__global__ __launch_bounds__(256, 2)
void gemm1_tc() {
    extern __shared__ char smem[];
    const uint32_t sb = smem_u32(smem);
    const int b = blockIdx.z;
    const size_t aoff = ((size_t)b * CDIM + blockIdx.y * BM) * HW;
    const size_t boff = ((size_t)b * CDIM + blockIdx.x * BN) * HW;

    float acc[4][4][4];
    mainloop<false>(sb, acc, g_depth_hi + aoff, g_depth_lo + aoff,
                    g_rgb_hi + boff, g_rgb_lo + boff, HW, HW, HW / BK);

    const int lane = threadIdx.x & 31, wid = threadIdx.x >> 5;
    const int wm = wid >> 2, wn = wid & 3;
    const int r0 = blockIdx.y * BM + wm * 64 + (lane >> 2);
    const int c0 = blockIdx.x * BN + wn * 32 + (lane & 3) * 2;
    __nv_bfloat16* ih = g_inter_hi + (size_t)b * CDIM * CDIM;
    __nv_bfloat16* il = g_inter_lo + (size_t)b * CDIM * CDIM;
#pragma unroll
    for (int t = 0; t < 4; ++t) {
#pragma unroll
        for (int nidx = 0; nidx < 4; ++nidx) {
            const int n = c0 + nidx * 8;
#pragma unroll
            for (int half = 0; half < 2; ++half) {
                const int m = r0 + t * 16 + half * 8;
                const float v0 = sigmoidf(acc[t][nidx][half * 2 + 0]);
                const float v1 = sigmoidf(acc[t][nidx][half * 2 + 1]);
                const __nv_bfloat16 h0 = __float2bfloat16(v0);
                const __nv_bfloat16 h1 = __float2bfloat16(v1);
                const __nv_bfloat16 l0 = __float2bfloat16(v0 - __bfloat162float(h0));
                const __nv_bfloat16 l1 = __float2bfloat16(v1 - __bfloat162float(h1));
                const size_t idx = (size_t)m * CDIM + n;
                *(__nv_bfloat162*)(ih + idx) = __nv_bfloat162(h0, h1);
                *(__nv_bfloat162*)(il + idx) = __nv_bfloat162(l0, l1);
            }
        }
    }
}

// ---------------------------------------------------------------------------
// GEMM2: out = rgb + inter @ depth (B via ldsm.trans on straight layout)
// grid (32, 4, 16), 256 threads
// ---------------------------------------------------------------------------
__global__ __launch_bounds__(256, 2)
void gemm2_tc(const float* __restrict__ rgb, float* __restrict__ out) {
    extern __shared__ char smem[];
    const uint32_t sb = smem_u32(smem);
    const int b = blockIdx.z;
    const size_t aoff = ((size_t)b * CDIM + blockIdx.y * BM) * CDIM;
    const size_t boff = (size_t)b * CDIM * HW + blockIdx.x * BN; // [b, d=0, s=nblk]

    float acc[4][4][4];
    mainloop<true>(sb, acc, g_inter_hi + aoff, g_inter_lo + aoff,
                   g_depth_hi + boff, g_depth_lo + boff, CDIM, HW, CDIM / BK);

    const int lane = threadIdx.x & 31, wid = threadIdx.x >> 5;
    const int wm = wid >> 2, wn = wid & 3;
    const int r0 = blockIdx.y * BM + wm * 64 + (lane >> 2);
    const int c0 = blockIdx.x * BN + wn * 32 + (lane & 3) * 2;
    const size_t base = (size_t)b * CDIM * HW;
#pragma unroll
    for (int t = 0; t < 4; ++t) {
#pragma unroll
        for (int nidx = 0; nidx < 4; ++nidx) {
            const int n = c0 + nidx * 8;
#pragma unroll
            for (int half = 0; half < 2; ++half) {
                const int m = r0 + t * 16 + half * 8;
                const size_t idx = base + (size_t)m * HW + n;
                const float2 rv = *(const float2*)(rgb + idx);
                float2 v;
                v.x = acc[t][nidx][half * 2 + 0] + rv.x;
                v.y = acc[t][nidx][half * 2 + 1] + rv.y;
                *(float2*)(out + idx) = v;
            }
        }
    }
}

// ---------------------------------------------------------------------------
// Split both inputs: fp32 -> bf16 hi/lo, 8 elems/thread each
// ---------------------------------------------------------------------------
__global__ __launch_bounds__(256)
void split_kernel(const float* __restrict__ rgb, const float* __restrict__ depth) {
    const size_t i = ((size_t)blockIdx.x * 256 + threadIdx.x) * 8;
#pragma unroll
    for (int which = 0; which < 2; ++which) {
        const float* src = which ? depth : rgb;
        __nv_bfloat16* dh = which ? g_depth_hi : g_rgb_hi;
        __nv_bfloat16* dl = which ? g_depth_lo : g_rgb_lo;
        float4 a = *(const float4*)(src + i);
        float4 c = *(const float4*)(src + i + 4);
        float v[8] = {a.x, a.y, a.z, a.w, c.x, c.y, c.z, c.w};
        union { __nv_bfloat16 h[8]; uint4 u; } H, L;
#pragma unroll
        for (int j = 0; j < 8; ++j) {
            __nv_bfloat16 hb = __float2bfloat16(v[j]);
            H.h[j] = hb;
            L.h[j] = __float2bfloat16(v[j] - __bfloat162float(hb));
        }
        *(uint4*)(dh + i) = H.u;
        *(uint4*)(dl + i) = L.u;
    }
}

// ---------------------------------------------------------------------------
// Launch
// ---------------------------------------------------------------------------
extern "C" void kernel_launch(void* const* d_in, const int* in_sizes, int n_in,
                              void* d_out, int out_size) {
    const float* rgb   = (const float*)d_in[0];
    const float* depth = (const float*)d_in[1];
    float* out = (float*)d_out;

    cudaFuncSetAttribute(gemm1_tc,
                         cudaFuncAttributeMaxDynamicSharedMemorySize, SMEM_TOTAL);
    cudaFuncSetAttribute(gemm2_tc,
                         cudaFuncAttributeMaxDynamicSharedMemorySize, SMEM_TOTAL);

    const size_t TOT = (size_t)BATCH * CDIM * HW;   // 33,554,432
    split_kernel<<<(unsigned)(TOT / 8 / 256), 256>>>(rgb, depth);

    gemm1_tc<<<dim3(CDIM / BN, CDIM / BM, BATCH), 256, SMEM_TOTAL>>>();
    gemm2_tc<<<dim3(HW / BN, CDIM / BM, BATCH), 256, SMEM_TOTAL>>>(rgb, out);
}